// round 1
// baseline (speedup 1.0000x reference)
#include <cuda_runtime.h>
#include <cstdint>

#define B_  8
#define L_  4096
#define D_  256
#define H_  128
#define M_  (B_*L_)          // 32768 positions

// ---------------- scratch (static __device__, no allocs) ----------------
__device__ float g_x   [M_*H_];      // 16 MB  projected features
__device__ float g_xgf [(size_t)M_*512]; // 64 MB gate preacts fwd
__device__ float g_xgb [(size_t)M_*512]; // 64 MB gate preacts bwd
__device__ float g_outf[M_*H_];      // 16 MB  lstm fwd outputs
__device__ float g_outb[M_*H_];      // 16 MB  lstm bwd outputs

// ---------------- helpers ----------------
__device__ __forceinline__ float sigf(float x) {
    return 1.0f / (1.0f + __expf(-x));
}
__device__ __forceinline__ float tanhfast(float x) {
    return 1.0f - 2.0f / (__expf(2.0f * x) + 1.0f);
}
__device__ __forceinline__ unsigned smem_u32(const void* p) {
    unsigned a;
    asm("{ .reg .u64 t; cvta.to.shared.u64 t, %1; cvt.u32.u64 %0, t; }"
        : "=r"(a) : "l"(p));
    return a;
}
#define FMA2(acc, w, h) \
    asm("fma.rn.f32x2 %0, %1, %2, %3;" : "=l"(acc) : "l"(w), "l"(h), "l"(acc))

// =====================================================================
// SGEMM:  C[M,N] = A[M,K] @ W[N,K]^T + b1[n] (+ b2[n])
// BM=128, BN=128, BK=8, 256 threads, 8x8 microtile
// =====================================================================
__global__ __launch_bounds__(256) void sgemm_bias_kernel(
    const float* __restrict__ A, const float* __restrict__ W,
    const float* __restrict__ b1, const float* __restrict__ b2,
    float* __restrict__ C, int M, int N, int K)
{
    __shared__ float As[8][128];
    __shared__ float Bs[8][128];
    const int bm = blockIdx.x * 128, bn = blockIdx.y * 128;
    const int t = threadIdx.x;
    const int tm = (t >> 4) * 8;      // 0..120
    const int tn = (t & 15) * 8;      // 0..120
    const int lrow = t >> 1, lcol = (t & 1) * 4;

    float acc[8][8];
#pragma unroll
    for (int i = 0; i < 8; i++)
#pragma unroll
        for (int j = 0; j < 8; j++) acc[i][j] = 0.f;

    for (int k0 = 0; k0 < K; k0 += 8) {
        float4 av = *(const float4*)(A + (size_t)(bm + lrow) * K + k0 + lcol);
        As[lcol + 0][lrow] = av.x; As[lcol + 1][lrow] = av.y;
        As[lcol + 2][lrow] = av.z; As[lcol + 3][lrow] = av.w;
        float4 wv = *(const float4*)(W + (size_t)(bn + lrow) * K + k0 + lcol);
        Bs[lcol + 0][lrow] = wv.x; Bs[lcol + 1][lrow] = wv.y;
        Bs[lcol + 2][lrow] = wv.z; Bs[lcol + 3][lrow] = wv.w;
        __syncthreads();
#pragma unroll
        for (int k = 0; k < 8; k++) {
            float4 a0 = *(const float4*)&As[k][tm];
            float4 a1 = *(const float4*)&As[k][tm + 4];
            float4 c0 = *(const float4*)&Bs[k][tn];
            float4 c1 = *(const float4*)&Bs[k][tn + 4];
            float a[8] = {a0.x, a0.y, a0.z, a0.w, a1.x, a1.y, a1.z, a1.w};
            float b[8] = {c0.x, c0.y, c0.z, c0.w, c1.x, c1.y, c1.z, c1.w};
#pragma unroll
            for (int i = 0; i < 8; i++)
#pragma unroll
                for (int j = 0; j < 8; j++) acc[i][j] += a[i] * b[j];
        }
        __syncthreads();
    }
    // epilogue
#pragma unroll
    for (int i = 0; i < 8; i++) {
        float* crow = C + (size_t)(bm + tm + i) * N + bn + tn;
#pragma unroll
        for (int j = 0; j < 8; j++) {
            int col = bn + tn + j;
            float v = acc[i][j] + b1[col];
            if (b2) v += b2[col];
            crow[j] = v;
        }
    }
}

// =====================================================================
// LSTM recurrence.  Grid = 64 CTAs = 16 clusters of 4 (one per (b,dir)).
// CTA rank owns hidden units [rank*32, rank*32+32) -> 128 gate rows.
// Thread tid: gate = tid>>5 (i,f,g,o), hl = tid&31.
// All 128 Whh weights of the row live in registers as 64 f32x2 pairs.
// Per step: dot with h (smem, double buffered) -> gpre smem -> warp0
// combines gates, updates c (register), writes h to all 4 CTAs' smem,
// cluster.sync.
// =====================================================================
__global__ void __cluster_dims__(4, 1, 1) __launch_bounds__(128, 1)
lstm_kernel(const float* __restrict__ xg_f, const float* __restrict__ xg_b,
            const float* __restrict__ Whh_f, const float* __restrict__ Whh_b,
            float* __restrict__ out_f, float* __restrict__ out_b)
{
    __shared__ __align__(16) float h_sm[2][H_];
    __shared__ float gpre[128];

    const int tid  = threadIdx.x;
    const int rank = blockIdx.x & 3;          // ctarank within 1-D cluster
    const int cid  = blockIdx.x >> 2;         // 0..15
    const int b    = cid >> 1;
    const int dir  = cid & 1;

    const float* xg   = dir ? xg_b  : xg_f;
    const float* Whh  = dir ? Whh_b : Whh_f;
    float*       outp = dir ? out_b : out_f;

    const int gate = tid >> 5, hl = tid & 31;
    const int r  = gate * 128 + rank * 32 + hl;   // global gate row 0..511
    const int hu = rank * 32 + tid;               // hidden unit for tid<32

    // weights into registers (64 packed f32x2)
    unsigned long long w[64];
    const unsigned long long* wrow =
        (const unsigned long long*)(Whh + (size_t)r * H_);
#pragma unroll
    for (int k = 0; k < 64; k++) w[k] = wrow[k];

    if (tid < H_) h_sm[0][tid] = 0.f;
    float c = 0.f;
    __syncthreads();
    asm volatile("barrier.cluster.arrive.aligned;" ::: "memory");
    asm volatile("barrier.cluster.wait.aligned;"   ::: "memory");

    const int t0 = dir ? (L_ - 1) : 0;
    const int dt = dir ? -1 : 1;
    const float* xptr = xg + r + (size_t)(b * L_ + t0) * 512;
    float xv_next = *xptr;

    for (int s = 0; s < L_; s++) {
        float xv = xv_next;
        xptr += (long)dt * 512;
        if (s + 1 < L_) xv_next = __ldg(xptr);   // prefetch, used next iter

        const int rb = s & 1;
        const ulonglong2* h2 = (const ulonglong2*)h_sm[rb];
        unsigned long long a0 = 0ull, a1 = 0ull, a2 = 0ull, a3 = 0ull;
#pragma unroll
        for (int k = 0; k < 16; k++) {
            ulonglong2 hv0 = h2[2 * k];
            ulonglong2 hv1 = h2[2 * k + 1];
            FMA2(a0, w[4 * k + 0], hv0.x);
            FMA2(a1, w[4 * k + 1], hv0.y);
            FMA2(a2, w[4 * k + 2], hv1.x);
            FMA2(a3, w[4 * k + 3], hv1.y);
        }
        float g = xv;
        g += __uint_as_float((unsigned)(a0 & 0xffffffffu)) + __uint_as_float((unsigned)(a0 >> 32));
        g += __uint_as_float((unsigned)(a1 & 0xffffffffu)) + __uint_as_float((unsigned)(a1 >> 32));
        g += __uint_as_float((unsigned)(a2 & 0xffffffffu)) + __uint_as_float((unsigned)(a2 >> 32));
        g += __uint_as_float((unsigned)(a3 & 0xffffffffu)) + __uint_as_float((unsigned)(a3 >> 32));

        gpre[tid] = g;
        __syncthreads();

        if (tid < 32) {
            float gi = gpre[tid];
            float gf = gpre[32 + tid];
            float gg = gpre[64 + tid];
            float go = gpre[96 + tid];
            c = sigf(gf) * c + sigf(gi) * tanhfast(gg);
            float h = sigf(go) * tanhfast(c);
            const int t = t0 + dt * s;
            outp[(size_t)(b * L_ + t) * H_ + hu] = h;
            // write h to the same slot in all 4 CTAs' next-buffer
            unsigned laddr = smem_u32(&h_sm[rb ^ 1][hu]);
#pragma unroll
            for (int p = 0; p < 4; p++) {
                unsigned ra;
                asm volatile("mapa.shared::cluster.u32 %0, %1, %2;"
                             : "=r"(ra) : "r"(laddr), "r"(p));
                asm volatile("st.shared::cluster.f32 [%0], %1;"
                             :: "r"(ra), "f"(h) : "memory");
            }
        }
        asm volatile("barrier.cluster.arrive.aligned;" ::: "memory");
        asm volatile("barrier.cluster.wait.aligned;"   ::: "memory");
    }
}

// =====================================================================
// Post MLP: hid = relu([out_f,out_b] @ W1^T + b1); p = sigmoid(hid.W2 + b2)
// block = 32 positions, 256 threads, each thread 4 pos x 4 hid.
// =====================================================================
__global__ __launch_bounds__(256) void post_kernel(
    const float* __restrict__ outf, const float* __restrict__ outb,
    const float* __restrict__ W1, const float* __restrict__ b1,
    const float* __restrict__ W2, const float* __restrict__ b2,
    float* __restrict__ probs)
{
    __shared__ float As[32][32];
    __shared__ float Bs[32][128];
    __shared__ float accsh[32];

    const int t = threadIdx.x;
    const int posb = blockIdx.x * 32;
    const int pb = (t >> 5) * 4;
    const int hb = (t & 31) * 4;

    float acc[4][4];
#pragma unroll
    for (int i = 0; i < 4; i++)
#pragma unroll
        for (int j = 0; j < 4; j++) acc[i][j] = 0.f;

    for (int kc = 0; kc < 256; kc += 32) {
        {   // stage 32x32 chunk of lstm_out
            int pl = t >> 3, k4 = (t & 7) * 4;
            const float* src = (kc < 128)
                ? (outf + (size_t)(posb + pl) * H_ + kc + k4)
                : (outb + (size_t)(posb + pl) * H_ + (kc - 128) + k4);
            *(float4*)&As[pl][k4] = *(const float4*)src;
        }
        {   // stage W1 chunk transposed: Bs[k][j] = W1[j][kc+k]
            int j = t >> 1, kk0 = (t & 1) * 16;
#pragma unroll
            for (int i = 0; i < 4; i++) {
                float4 v = *(const float4*)(W1 + (size_t)j * 256 + kc + kk0 + i * 4);
                Bs[kk0 + i * 4 + 0][j] = v.x;
                Bs[kk0 + i * 4 + 1][j] = v.y;
                Bs[kk0 + i * 4 + 2][j] = v.z;
                Bs[kk0 + i * 4 + 3][j] = v.w;
            }
        }
        __syncthreads();
#pragma unroll
        for (int k = 0; k < 32; k++) {
            float a0v = As[pb][k], a1v = As[pb + 1][k];
            float a2v = As[pb + 2][k], a3v = As[pb + 3][k];
            float4 bv = *(const float4*)&Bs[k][hb];
            acc[0][0] += a0v * bv.x; acc[0][1] += a0v * bv.y;
            acc[0][2] += a0v * bv.z; acc[0][3] += a0v * bv.w;
            acc[1][0] += a1v * bv.x; acc[1][1] += a1v * bv.y;
            acc[1][2] += a1v * bv.z; acc[1][3] += a1v * bv.w;
            acc[2][0] += a2v * bv.x; acc[2][1] += a2v * bv.y;
            acc[2][2] += a2v * bv.z; acc[2][3] += a2v * bv.w;
            acc[3][0] += a3v * bv.x; acc[3][1] += a3v * bv.y;
            acc[3][2] += a3v * bv.z; acc[3][3] += a3v * bv.w;
        }
        __syncthreads();
    }

    float w2v[4], b1v[4];
#pragma unroll
    for (int j = 0; j < 4; j++) { w2v[j] = W2[hb + j]; b1v[j] = b1[hb + j]; }

    float psum[4];
#pragma unroll
    for (int i = 0; i < 4; i++) {
        float s = 0.f;
#pragma unroll
        for (int j = 0; j < 4; j++) {
            float hv = acc[i][j] + b1v[j];
            hv = hv > 0.f ? hv : 0.f;
            s += hv * w2v[j];
        }
        psum[i] = s;
    }
    // warp reduce (each warp owns 4 exclusive positions)
#pragma unroll
    for (int off = 16; off > 0; off >>= 1)
#pragma unroll
        for (int i = 0; i < 4; i++)
            psum[i] += __shfl_down_sync(0xffffffffu, psum[i], off);
    if ((t & 31) == 0)
#pragma unroll
        for (int i = 0; i < 4; i++) accsh[pb + i] = psum[i];
    __syncthreads();

    if (t < 32) {
        int gp = posb + t;
        int l = gp & (L_ - 1);
        float v = accsh[t] + b2[0];
        float p = 1.0f / (1.0f + __expf(-v));
        if (l == 0 || l == L_ - 1) p *= 1.2f;
        p = fminf(fmaxf(p, 0.f), 1.f);
        probs[gp] = p;
    }
}

// =====================================================================
// adjacent-gradient adjustment
// =====================================================================
__global__ void adj_kernel(const float* __restrict__ probs,
                           float* __restrict__ adj)
{
    int i = blockIdx.x * blockDim.x + threadIdx.x;
    if (i >= M_) return;
    int l = i & (L_ - 1);
    float a = 0.f;
    if (l > 0 && l < L_ - 1) {
        float pm = probs[i - 1], pc = probs[i], pp = probs[i + 1];
        float lg = pc - pm, rg = pc - pp;
        if (lg < 0.f && fabsf(lg) > fabsf(rg))       a = -1.f;
        else if (rg < 0.f && fabsf(rg) > fabsf(lg))  a = 1.f;
    }
    adj[i] = a;
}

// =====================================================================
// launch
// =====================================================================
extern "C" void kernel_launch(void* const* d_in, const int* in_sizes, int n_in,
                              void* d_out, int out_size)
{
    const float* features = (const float*)d_in[0];
    const float* Wp    = (const float*)d_in[1];
    const float* bp    = (const float*)d_in[2];
    const float* Wih_f = (const float*)d_in[3];
    const float* Whh_f = (const float*)d_in[4];
    const float* bih_f = (const float*)d_in[5];
    const float* bhh_f = (const float*)d_in[6];
    const float* Wih_b = (const float*)d_in[7];
    const float* Whh_b = (const float*)d_in[8];
    const float* bih_b = (const float*)d_in[9];
    const float* bhh_b = (const float*)d_in[10];
    const float* W1    = (const float*)d_in[11];
    const float* b1    = (const float*)d_in[12];
    const float* W2    = (const float*)d_in[13];
    const float* b2    = (const float*)d_in[14];
    float* out = (float*)d_out;

    void *px, *pxgf, *pxgb, *pof, *pob;
    cudaGetSymbolAddress(&px,   g_x);
    cudaGetSymbolAddress(&pxgf, g_xgf);
    cudaGetSymbolAddress(&pxgb, g_xgb);
    cudaGetSymbolAddress(&pof,  g_outf);
    cudaGetSymbolAddress(&pob,  g_outb);
    float* xbuf  = (float*)px;
    float* xgf   = (float*)pxgf;
    float* xgb   = (float*)pxgb;
    float* outf  = (float*)pof;
    float* outb  = (float*)pob;

    // 1) projection: x = features @ Wp^T + bp   (M=32768, N=128, K=256)
    sgemm_bias_kernel<<<dim3(M_ / 128, 1), 256>>>(
        features, Wp, bp, nullptr, xbuf, M_, H_, D_);
    // 2) gate preacts per direction (M=32768, N=512, K=128)
    sgemm_bias_kernel<<<dim3(M_ / 128, 4), 256>>>(
        xbuf, Wih_f, bih_f, bhh_f, xgf, M_, 512, H_);
    sgemm_bias_kernel<<<dim3(M_ / 128, 4), 256>>>(
        xbuf, Wih_b, bih_b, bhh_b, xgb, M_, 512, H_);
    // 3) recurrence: 16 clusters of 4 CTAs
    lstm_kernel<<<64, 128>>>(xgf, xgb, Whh_f, Whh_b, outf, outb);
    // 4) post MLP -> probs (first 32768 floats of d_out)
    post_kernel<<<M_ / 32, 256>>>(outf, outb, W1, b1, W2, b2, out);
    // 5) adj (second 32768 floats)
    adj_kernel<<<M_ / 256, 256>>>(out, out + M_);
}